// round 15
// baseline (speedup 1.0000x reference)
#include <cuda_runtime.h>
#include <stdint.h>

typedef unsigned long long u64;
typedef unsigned int u32;

// ---------------- cmem: small uniform-read constants ----------------
__constant__ __align__(16) float cW3[16 * 8];
__constant__ __align__(16) float cW4[8 * 3];
__constant__ __align__(16) float cB3[8];
__constant__ __align__(16) float cB4[3];
__constant__ __align__(16) float cEnc[27];

// fp16-converted grids: [2][256*256*16 u32 words]
__device__ __align__(16) u32 g_f16[2 * 1048576];

// ---------------- dyn smem layout (byte offsets) ----------------
#define OFFB_W1P 0        // [n=64][16] u64 pairs (b0,b1), row stride 20 u64
#define OFFB_W2P 10240    // [n=16][16] u64 pairs, stride 20 u64
#define OFFB_B1 12800     // 64 f32
#define OFFB_META 13120   // [warp][32 rows][12 u32]  (8 used)
#define OFFB_STAGE 19264  // [warp][32 rows][32 words] u32
#define DYN_BYTES 35648

// stage rotation (words, multiple of 4): conflict-free for STS.128 writes,
// LDSM 8-row reads simultaneously.
#define ROT(row) ((((row) & 1) << 4) | (((row) & 6) << 1))

// ---------------- helpers ----------------
static __device__ __forceinline__ u32 packh2(float lo, float hi) {
    u32 d; asm("cvt.rn.f16x2.f32 %0, %1, %2;" : "=r"(d) : "f"(hi), "f"(lo)); return d;
}
static __device__ __forceinline__ u32 hfma2(u32 a, u32 b, u32 c) {
    u32 d; asm("fma.rn.f16x2 %0, %1, %2, %3;" : "=r"(d) : "r"(a), "r"(b), "r"(c)); return d;
}
static __device__ __forceinline__ u32 prmt_hi2(u32 a) {  // [b3b2|b3b2]
    u32 d; asm("prmt.b32 %0, %1, %1, 0x3232;" : "=r"(d) : "r"(a)); return d;
}
static __device__ __forceinline__ void mma_f16(float *d, u32 a0, u32 a1, u32 a2, u32 a3,
                                               u32 b0, u32 b1) {
    asm("mma.sync.aligned.m16n8k16.row.col.f32.f16.f16.f32 "
        "{%0,%1,%2,%3},{%4,%5,%6,%7},{%8,%9},{%0,%1,%2,%3};"
        : "+f"(d[0]), "+f"(d[1]), "+f"(d[2]), "+f"(d[3])
        : "r"(a0), "r"(a1), "r"(a2), "r"(a3), "r"(b0), "r"(b1));
}
static __device__ __forceinline__ void mma_f16k8(float *d, u32 a0, u32 a1, u32 b0) {
    asm("mma.sync.aligned.m16n8k8.row.col.f32.f16.f16.f32 "
        "{%0,%1,%2,%3},{%4,%5},{%6},{%0,%1,%2,%3};"
        : "+f"(d[0]), "+f"(d[1]), "+f"(d[2]), "+f"(d[3])
        : "r"(a0), "r"(a1), "r"(b0));
}
static __device__ __forceinline__ void ldsm4(u32 &r0, u32 &r1, u32 &r2, u32 &r3, u32 addr) {
    asm volatile("ldmatrix.sync.aligned.m8n8.x4.shared.b16 {%0,%1,%2,%3}, [%4];"
                 : "=r"(r0), "=r"(r1), "=r"(r2), "=r"(r3) : "r"(addr));
}
static __device__ __forceinline__ u32 smem_u32(const void *p) {
    u32 a;
    asm("{ .reg .u64 t; cvta.to.shared.u64 t, %1; cvt.u32.u64 %0, t; }" : "=r"(a) : "l"(p));
    return a;
}
static __device__ __forceinline__ void sts128u(u32 addr, u32 a, u32 b, u32 c, u32 d) {
    asm volatile("st.shared.v4.u32 [%0], {%1,%2,%3,%4};"
                 :: "r"(addr), "r"(a), "r"(b), "r"(c), "r"(d) : "memory");
}
static __device__ __forceinline__ float leaky(float x) { return fmaxf(x, 0.01f * x); }
static __device__ __forceinline__ float sigmoidf(float x) { return 1.0f / (1.0f + __expf(-x)); }
static __device__ __forceinline__ float tanh_fast(float x) {
    return fmaf(2.0f, sigmoidf(2.0f * x), -1.0f);
}
static __device__ __forceinline__ void encode(float i0, float i1, float &x, float &y) {
    float h[4];
#pragma unroll
    for (int j = 0; j < 4; j++)
        h[j] = tanh_fast(fmaf(i0, cEnc[j], fmaf(i1, cEnc[4 + j], cEnc[8 + j])));
    float z0 = cEnc[24], z1 = cEnc[25];
#pragma unroll
    for (int j = 0; j < 4; j++) {
        z0 = fmaf(h[j], cEnc[12 + j * 3 + 0], z0);
        z1 = fmaf(h[j], cEnc[12 + j * 3 + 1], z1);
    }
    x = sigmoidf(z0) * 255.0f;
    y = sigmoidf(z1) * 255.0f;
}

// ---------------- grid pre-conversion: fp32 -> fp16x2 ----------------
__global__ void __launch_bounds__(256) convert_grids(
    const float *__restrict__ g0, const float *__restrict__ g1)
{
    int i = blockIdx.x * 256 + threadIdx.x;
    const float *src = (i < 524288) ? g0 : g1;
    int j = i & 524287;
    float4 v = __ldg((const float4 *)src + j);
    u64 w = (u64)packh2(v.x, v.y) | ((u64)packh2(v.z, v.w) << 32);
    *((u64 *)g_f16 + i) = w;
}

// ---------------- main kernel ----------------
__global__ void __launch_bounds__(128, 5) gridnet_mmahead(
    const float *__restrict__ pos, const float *__restrict__ dir,
    const float *__restrict__ fc_w1, const float *__restrict__ fc_b1,
    const float *__restrict__ fc_w2, const float *__restrict__ fc_b2,
    float *__restrict__ out, int n, int ntiles)
{
    extern __shared__ __align__(16) char smraw[];

    const int tid = threadIdx.x;
    const int warp = tid >> 5, lane = tid & 31;
    const int r = lane >> 2, c = lane & 3;  // loader and mma fragment roles

    // ---- stage W1/W2 once per CTA: u64-packed (b0,b1) pairs, stride 20 u64
    for (int i = tid; i < 64 * 16; i += 128) {
        int nn = i >> 4, idx = i & 15;  // idx = 4*kt + c
        int kt = idx >> 2, cc = idx & 3;
        int w0k2 = 8 * kt + cc, w1k2 = w0k2 + 4;
        u32 lo = packh2(fc_w1[(2 * w0k2) * 64 + nn], fc_w1[(2 * w0k2 + 1) * 64 + nn]);
        u32 hi = packh2(fc_w1[(2 * w1k2) * 64 + nn], fc_w1[(2 * w1k2 + 1) * 64 + nn]);
        *(u64 *)(smraw + OFFB_W1P + ((u32)(nn * 20 + idx) * 8)) = (u64)lo | ((u64)hi << 32);
    }
    for (int i = tid; i < 16 * 16; i += 128) {
        int nn = i >> 4, idx = i & 15;
        int kt = idx >> 2, cc = idx & 3;
        int w0k2 = 8 * kt + cc, w1k2 = w0k2 + 4;
        u32 lo = packh2(fc_w2[(2 * w0k2) * 16 + nn], fc_w2[(2 * w0k2 + 1) * 16 + nn]);
        u32 hi = packh2(fc_w2[(2 * w1k2) * 16 + nn], fc_w2[(2 * w1k2 + 1) * 16 + nn]);
        *(u64 *)(smraw + OFFB_W2P + ((u32)(nn * 20 + idx) * 8)) = (u64)lo | ((u64)hi << 32);
    }
    if (tid < 64) *(float *)(smraw + OFFB_B1 + tid * 4) = fc_b1[tid];
    __syncthreads();

    const float *sB1 = (const float *)(smraw + OFFB_B1);
    u32 *sx = (u32 *)(smraw + OFFB_STAGE) + warp * 1024;
    const u32 sx_addr = smem_u32(sx);
    u32 *meta = (u32 *)(smraw + OFFB_META) + warp * 384;  // [32][12]
    const u32 meta_addr = smem_u32(meta);

    // ldmatrix role precompute
    const int mi = lane >> 3, rr = lane & 7;
    const int rotA = ROT(rr);
    const u32 baseA = sx_addr + (u32)(((mi & 1) * 8 + rr) * 128);
    const u32 baseB = baseA + 16 * 128;
    const int khalf = (mi >> 1) * 4;

    // ---- hoisted per-lane head constants (loop-invariant)
    const float b2a = fc_b2[2 * c], b2b = fc_b2[2 * c + 1];
    const float b2e = fc_b2[8 + 2 * c], b2f = fc_b2[8 + 2 * c + 1];
    const float b3a = cB3[2 * c], b3b = cB3[2 * c + 1];
    float b4a = 0.0f, b4b = 0.0f;
    if (c == 0) { b4a = cB4[0]; b4b = cB4[1]; }
    else if (c == 1) { b4a = cB4[2]; }
    const u32 w3b0 = packh2(cW3[(2 * c) * 8 + r], cW3[(2 * c + 1) * 8 + r]);
    const u32 w3b1 = packh2(cW3[(2 * c + 8) * 8 + r], cW3[(2 * c + 9) * 8 + r]);
    const u32 w4b = packh2((r < 3) ? cW4[(2 * c) * 3 + r] : 0.0f,
                           (r < 3) ? cW4[(2 * c + 1) * 3 + r] : 0.0f);

    // prefetch first tile's coords
    int tile = blockIdx.x;
    float2 pco, dco;
    {
        int pc0 = min(tile * 128 + warp * 32 + lane, n - 1);
        pco = *(const float2 *)(pos + 2 * pc0);
        dco = *(const float2 *)(dir + 2 * pc0);
    }

    for (; tile < ntiles; tile += gridDim.x) {
        float2 pcur = pco, dcur = dco;
        int tnext = tile + gridDim.x;
        if (tnext < ntiles) {
            int pcn = min(tnext * 128 + warp * 32 + lane, n - 1);
            pco = *(const float2 *)(pos + 2 * pcn);
            dco = *(const float2 *)(dir + 2 * pcn);
        }

        // ===== owner: encode -> packed u32 corner metadata (cell16 | f16w<<16) =====
        {
            float gx[2], gy[2];
            encode(pcur.x, pcur.y, gx[0], gy[0]);
            encode(dcur.x, dcur.y, gx[1], gy[1]);
#pragma unroll
            for (int g = 0; g < 2; g++) {
                float x = gx[g], y = gy[g];
                int x0 = min((int)x, 255), y0 = min((int)y, 255);
                float xf = x - (float)x0, yf = y - (float)y0;
                int x1 = min(x0 + 1, 255), y1 = min(y0 + 1, 255);
                u32 c0 = (u32)(y0 * 256 + x0);
                u32 c1 = (u32)(y0 * 256 + x1);
                u32 c2 = (u32)(y1 * 256 + x0);
                u32 c3 = (u32)(y1 * 256 + x1);
                float w0 = (1.0f - xf) * (1.0f - yf);
                float w1 = xf * (1.0f - yf);
                float w2 = (1.0f - xf) * yf;
                float w3 = xf * yf;
                u32 m0 = c0 | (packh2(w0, 0.0f) << 16);
                u32 m1 = c1 | (packh2(w1, 0.0f) << 16);
                u32 m2 = c2 | (packh2(w2, 0.0f) << 16);
                u32 m3 = c3 | (packh2(w3, 0.0f) << 16);
                sts128u(meta_addr + (u32)(lane * 48 + g * 16), m0, m1, m2, m3);
            }
        }
        __syncwarp();

        // ===== loader: 4 lanes/row, LDG.128 gather + fp16x2 blend -> rotated stage =====
#pragma unroll 1
        for (int g = 0; g < 2; g++) {
            const char *gbase = (const char *)(g_f16 + (u32)g * 1048576u);
#pragma unroll
            for (int i = 0; i < 4; i++) {
                int row = i * 8 + r;
                uint4 mg = *(const uint4 *)(meta + row * 12 + g * 4);
                u32 a0 = 0, a1 = 0, a2 = 0, a3 = 0;
#pragma unroll
                for (int cc = 0; cc < 4; cc++) {
                    u32 m = (cc == 0) ? mg.x : (cc == 1) ? mg.y : (cc == 2) ? mg.z : mg.w;
                    u32 wb = prmt_hi2(m);
                    u32 off = (m & 0xFFFFu) << 6;
                    uint4 v = __ldg((const uint4 *)(gbase + off) + c);
                    a0 = hfma2(v.x, wb, a0);
                    a1 = hfma2(v.y, wb, a1);
                    a2 = hfma2(v.z, wb, a2);
                    a3 = hfma2(v.w, wb, a3);
                }
                int word = row * 32 + ((g * 16 + 4 * c + ROT(row)) & 31);
                sts128u(sx_addr + (u32)(word * 4), a0, a1, a2, a3);
            }
        }
        __syncwarp();

        // ===== FC1 + FC2 fused: A-frags hoisted once, nt-quarters (d1[16]) =====
        u32 A[32];  // [kt][8]
#pragma unroll
        for (int kt = 0; kt < 4; kt++) {
            u32 wo = (u32)(((8 * kt + khalf + rotA) & 31) * 4);
            ldsm4(A[kt * 8 + 0], A[kt * 8 + 1], A[kt * 8 + 2], A[kt * 8 + 3], baseA + wo);
            ldsm4(A[kt * 8 + 4], A[kt * 8 + 5], A[kt * 8 + 6], A[kt * 8 + 7], baseB + wo);
        }

        float d2[16];
#pragma unroll
        for (int q = 0; q < 16; q++) d2[q] = 0.0f;

#pragma unroll 1
        for (int q = 0; q < 4; q++) {   // nt pair (2q, 2q+1); FC2 k-tile = q
            float d1[16];
#pragma unroll
            for (int z = 0; z < 16; z++) d1[z] = 0.0f;
#pragma unroll
            for (int kt = 0; kt < 4; kt++) {
#pragma unroll
                for (int ntp = 0; ntp < 2; ntp++) {
                    int nt = 2 * q + ntp;
                    u64 bb = *(const u64 *)(smraw + OFFB_W1P +
                                            (u32)(((8 * nt + r) * 20 + 4 * kt + c) * 8));
                    u32 b0 = (u32)bb, b1 = (u32)(bb >> 32);
                    mma_f16(d1 + ntp * 8, A[kt * 8 + 0], A[kt * 8 + 1], A[kt * 8 + 2],
                            A[kt * 8 + 3], b0, b1);
                    mma_f16(d1 + ntp * 8 + 4, A[kt * 8 + 4], A[kt * 8 + 5], A[kt * 8 + 6],
                            A[kt * 8 + 7], b0, b1);
                }
            }
            // FC2 partial: this quarter's D1 = A-frags for k-tile q
            int ntA0 = 2 * q, ntA1 = 2 * q + 1;
            float blo0 = sB1[8 * ntA0 + 2 * c];
            float bhi0 = sB1[8 * ntA0 + 2 * c + 1];
            float blo1 = sB1[8 * ntA1 + 2 * c];
            float bhi1 = sB1[8 * ntA1 + 2 * c + 1];
            u32 a0 = packh2(leaky(d1[0] + blo0), leaky(d1[1] + bhi0));
            u32 a1 = packh2(leaky(d1[2] + blo0), leaky(d1[3] + bhi0));
            u32 a2 = packh2(leaky(d1[8] + blo1), leaky(d1[9] + bhi1));
            u32 a3 = packh2(leaky(d1[10] + blo1), leaky(d1[11] + bhi1));
            u32 a10 = packh2(leaky(d1[4] + blo0), leaky(d1[5] + bhi0));
            u32 a11 = packh2(leaky(d1[6] + blo0), leaky(d1[7] + bhi0));
            u32 a12 = packh2(leaky(d1[12] + blo1), leaky(d1[13] + bhi1));
            u32 a13 = packh2(leaky(d1[14] + blo1), leaky(d1[15] + bhi1));
#pragma unroll
            for (int nt2 = 0; nt2 < 2; nt2++) {
                u64 bb = *(const u64 *)(smraw + OFFB_W2P +
                                        (u32)(((8 * nt2 + r) * 20 + 4 * q + c) * 8));
                u32 b0 = (u32)bb, b1 = (u32)(bb >> 32);
                mma_f16(d2 + nt2 * 8, a0, a1, a2, a3, b0, b1);
                mma_f16(d2 + nt2 * 8 + 4, a10, a11, a12, a13, b0, b1);
            }
        }

        // ===== head entirely in MMA fragments: FC3 (2x k16) + FC4 (2x k8) =====
        // FC3 rows 0-15: A-frags from d2 (cols 2c,2c+1 block + cols 8+2c block)
        float d3a[4] = {0.f, 0.f, 0.f, 0.f}, d3b[4] = {0.f, 0.f, 0.f, 0.f};
        {
            u32 h0 = packh2(leaky(d2[0] + b2a), leaky(d2[1] + b2b));
            u32 h1 = packh2(leaky(d2[2] + b2a), leaky(d2[3] + b2b));
            u32 h2 = packh2(leaky(d2[8] + b2e), leaky(d2[9] + b2f));
            u32 h3 = packh2(leaky(d2[10] + b2e), leaky(d2[11] + b2f));
            mma_f16(d3a, h0, h1, h2, h3, w3b0, w3b1);
            u32 g0 = packh2(leaky(d2[4] + b2a), leaky(d2[5] + b2b));
            u32 g1 = packh2(leaky(d2[6] + b2a), leaky(d2[7] + b2b));
            u32 g2 = packh2(leaky(d2[12] + b2e), leaky(d2[13] + b2f));
            u32 g3 = packh2(leaky(d2[14] + b2e), leaky(d2[15] + b2f));
            mma_f16(d3b, g0, g1, g2, g3, w3b0, w3b1);
        }
        float d4a[4] = {0.f, 0.f, 0.f, 0.f}, d4b[4] = {0.f, 0.f, 0.f, 0.f};
        {
            u32 h0 = packh2(leaky(d3a[0] + b3a), leaky(d3a[1] + b3b));
            u32 h1 = packh2(leaky(d3a[2] + b3a), leaky(d3a[3] + b3b));
            mma_f16k8(d4a, h0, h1, w4b);
            u32 g0 = packh2(leaky(d3b[0] + b3a), leaky(d3b[1] + b3b));
            u32 g1 = packh2(leaky(d3b[2] + b3a), leaky(d3b[3] + b3b));
            mma_f16k8(d4b, g0, g1, w4b);
        }

        // ===== outputs: fragment owners store directly =====
        {
            const int ptb = tile * 128 + warp * 32 + r;
            if (c == 0) {
#pragma unroll
                for (int h = 0; h < 4; h++) {
                    float v0 = (h < 2) ? d4a[2 * h] : d4b[2 * (h - 2)];
                    float v1 = (h < 2) ? d4a[2 * h + 1] : d4b[2 * (h - 2) + 1];
                    int pt = ptb + 8 * h;
                    if (pt < n) {
                        out[pt * 3 + 0] = sigmoidf(leaky(v0 + b4a)) * 255.0f;
                        out[pt * 3 + 1] = sigmoidf(leaky(v1 + b4b)) * 255.0f;
                    }
                }
            } else if (c == 1) {
#pragma unroll
                for (int h = 0; h < 4; h++) {
                    float v0 = (h < 2) ? d4a[2 * h] : d4b[2 * (h - 2)];
                    int pt = ptb + 8 * h;
                    if (pt < n)
                        out[pt * 3 + 2] = sigmoidf(leaky(v0 + b4a)) * 255.0f;
                }
            }
        }
        __syncwarp();  // stage/meta reuse across tiles
    }
}

extern "C" void kernel_launch(void *const *d_in, const int *in_sizes, int n_in,
                              void *d_out, int out_size)
{
    const float *pos = (const float *)d_in[0];
    const float *dir = (const float *)d_in[1];
    const float *pos_grid = (const float *)d_in[2];
    const float *dir_grid = (const float *)d_in[3];

    cudaMemcpyToSymbolAsync(cEnc, d_in[4], 8 * sizeof(float), 0, cudaMemcpyDeviceToDevice, 0);
    cudaMemcpyToSymbolAsync(cEnc, d_in[5], 4 * sizeof(float), 8 * sizeof(float), cudaMemcpyDeviceToDevice, 0);
    cudaMemcpyToSymbolAsync(cEnc, d_in[6], 12 * sizeof(float), 12 * sizeof(float), cudaMemcpyDeviceToDevice, 0);
    cudaMemcpyToSymbolAsync(cEnc, d_in[7], 3 * sizeof(float), 24 * sizeof(float), cudaMemcpyDeviceToDevice, 0);
    cudaMemcpyToSymbolAsync(cW3, d_in[12], 16 * 8 * sizeof(float), 0, cudaMemcpyDeviceToDevice, 0);
    cudaMemcpyToSymbolAsync(cB3, d_in[13], 8 * sizeof(float), 0, cudaMemcpyDeviceToDevice, 0);
    cudaMemcpyToSymbolAsync(cW4, d_in[14], 8 * 3 * sizeof(float), 0, cudaMemcpyDeviceToDevice, 0);
    cudaMemcpyToSymbolAsync(cB4, d_in[15], 3 * sizeof(float), 0, cudaMemcpyDeviceToDevice, 0);

    convert_grids<<<4096, 256>>>(pos_grid, dir_grid);

    cudaFuncSetAttribute(gridnet_mmahead, cudaFuncAttributeMaxDynamicSharedMemorySize, DYN_BYTES);

    float *out = (float *)d_out;
    int n = in_sizes[0] / 2;
    int ntiles = (n + 127) / 128;
    int blocks = 148 * 5;
    if (blocks > ntiles) blocks = ntiles;
    gridnet_mmahead<<<blocks, 128, DYN_BYTES>>>(
        pos, dir,
        (const float *)d_in[8], (const float *)d_in[9],
        (const float *)d_in[10], (const float *)d_in[11],
        out, n, ntiles);
}

// round 16
// speedup vs baseline: 1.0975x; 1.0975x over previous
#include <cuda_runtime.h>
#include <stdint.h>

typedef unsigned long long u64;
typedef unsigned int u32;

// ---------------- cmem: small uniform-read constants ----------------
__constant__ __align__(16) float cW3[16 * 8];
__constant__ __align__(16) float cW4[8 * 3];
__constant__ __align__(16) float cB3[8];
__constant__ __align__(16) float cB4[3];
__constant__ __align__(16) float cEnc[27];

// fp16-converted grids: [2][256*256*16 u32 words]
__device__ __align__(16) u32 g_f16[2 * 1048576];

// ---------------- dyn smem layout (byte offsets) ----------------
// W1 B-frags: [nt=8][kt=4][lane=32] u64  -> one fragment read = 32 consecutive u64
#define OFFB_W1P 0        // 8*4*32*8 = 8192
#define OFFB_W2P 8192     // [nt2=2][kt=4][lane=32] u64 = 2048
#define OFFB_B1 10240     // 64 f32
#define OFFB_B2 10496     // 16 f32
#define OFFB_META 10560   // [warp][32 rows][12 u32] (8 used) = 6144
#define OFFB_STAGE 16704  // [warp][32 rows][32 words] u32 = 16384
#define DYN_BYTES 33088

// stage rotation (words, multiple of 4): conflict-free for STS.128 writes,
// LDSM 8-row reads, H2 restage and head readback simultaneously.
#define ROT(row) ((((row) & 1) << 4) | (((row) & 6) << 1))

// ---------------- helpers ----------------
static __device__ __forceinline__ u64 pack2(float lo, float hi) {
    u64 r; asm("mov.b64 %0, {%1, %2};" : "=l"(r) : "f"(lo), "f"(hi)); return r;
}
static __device__ __forceinline__ float2 unpack2(u64 v) {
    float2 f; asm("mov.b64 {%0, %1}, %2;" : "=f"(f.x), "=f"(f.y) : "l"(v)); return f;
}
static __device__ __forceinline__ void fma2(u64 &d, u64 a, u64 b) {
    asm("fma.rn.f32x2 %0, %1, %2, %0;" : "+l"(d) : "l"(a), "l"(b));
}
static __device__ __forceinline__ u32 packh2(float lo, float hi) {
    u32 d; asm("cvt.rn.f16x2.f32 %0, %1, %2;" : "=r"(d) : "f"(hi), "f"(lo)); return d;
}
static __device__ __forceinline__ u32 hfma2(u32 a, u32 b, u32 c) {
    u32 d; asm("fma.rn.f16x2 %0, %1, %2, %3;" : "=r"(d) : "r"(a), "r"(b), "r"(c)); return d;
}
static __device__ __forceinline__ u32 prmt_hi2(u32 a) {  // [b3b2|b3b2]
    u32 d; asm("prmt.b32 %0, %1, %1, 0x3232;" : "=r"(d) : "r"(a)); return d;
}
static __device__ __forceinline__ void mma_f16(float *d, u32 a0, u32 a1, u32 a2, u32 a3,
                                               u32 b0, u32 b1) {
    asm("mma.sync.aligned.m16n8k16.row.col.f32.f16.f16.f32 "
        "{%0,%1,%2,%3},{%4,%5,%6,%7},{%8,%9},{%0,%1,%2,%3};"
        : "+f"(d[0]), "+f"(d[1]), "+f"(d[2]), "+f"(d[3])
        : "r"(a0), "r"(a1), "r"(a2), "r"(a3), "r"(b0), "r"(b1));
}
static __device__ __forceinline__ void ldsm4(u32 &r0, u32 &r1, u32 &r2, u32 &r3, u32 addr) {
    asm volatile("ldmatrix.sync.aligned.m8n8.x4.shared.b16 {%0,%1,%2,%3}, [%4];"
                 : "=r"(r0), "=r"(r1), "=r"(r2), "=r"(r3) : "r"(addr));
}
static __device__ __forceinline__ u32 smem_u32(const void *p) {
    u32 a;
    asm("{ .reg .u64 t; cvta.to.shared.u64 t, %1; cvt.u32.u64 %0, t; }" : "=r"(a) : "l"(p));
    return a;
}
static __device__ __forceinline__ void sts128u(u32 addr, u32 a, u32 b, u32 c, u32 d) {
    asm volatile("st.shared.v4.u32 [%0], {%1,%2,%3,%4};"
                 :: "r"(addr), "r"(a), "r"(b), "r"(c), "r"(d) : "memory");
}
static __device__ __forceinline__ float leaky(float x) { return fmaxf(x, 0.01f * x); }
static __device__ __forceinline__ float sigmoidf(float x) { return 1.0f / (1.0f + __expf(-x)); }
static __device__ __forceinline__ float tanh_fast(float x) {
    return fmaf(2.0f, sigmoidf(2.0f * x), -1.0f);
}
static __device__ __forceinline__ void encode(float i0, float i1, float &x, float &y) {
    float h[4];
#pragma unroll
    for (int j = 0; j < 4; j++)
        h[j] = tanh_fast(fmaf(i0, cEnc[j], fmaf(i1, cEnc[4 + j], cEnc[8 + j])));
    float z0 = cEnc[24], z1 = cEnc[25];
#pragma unroll
    for (int j = 0; j < 4; j++) {
        z0 = fmaf(h[j], cEnc[12 + j * 3 + 0], z0);
        z1 = fmaf(h[j], cEnc[12 + j * 3 + 1], z1);
    }
    x = sigmoidf(z0) * 255.0f;
    y = sigmoidf(z1) * 255.0f;
}

// ---------------- grid pre-conversion: fp32 -> fp16x2 ----------------
__global__ void __launch_bounds__(256) convert_grids(
    const float *__restrict__ g0, const float *__restrict__ g1)
{
    int i = blockIdx.x * 256 + threadIdx.x;
    const float *src = (i < 524288) ? g0 : g1;
    int j = i & 524287;
    float4 v = __ldg((const float4 *)src + j);
    u64 w = (u64)packh2(v.x, v.y) | ((u64)packh2(v.z, v.w) << 32);
    *((u64 *)g_f16 + i) = w;
}

// ---------------- main kernel ----------------
__global__ void __launch_bounds__(128, 5) gridnet_cfb(
    const float *__restrict__ pos, const float *__restrict__ dir,
    const float *__restrict__ fc_w1, const float *__restrict__ fc_b1,
    const float *__restrict__ fc_w2, const float *__restrict__ fc_b2,
    float *__restrict__ out, int n, int ntiles)
{
    extern __shared__ __align__(16) char smraw[];

    const int tid = threadIdx.x;
    const int warp = tid >> 5, lane = tid & 31;
    const int r = lane >> 2, c = lane & 3;  // loader and mma fragment roles

    // ---- stage W1: [nt][kt][lane] u64 (b0,b1) pairs, conflict-free frag reads
    for (int i = tid; i < 64 * 16; i += 128) {
        int nn = i >> 4, idx = i & 15;  // nn = 8*nt + r', idx = 4*kt + c'
        int kt = idx >> 2, cc = idx & 3;
        int w0k2 = 8 * kt + cc, w1k2 = w0k2 + 4;
        u32 lo = packh2(fc_w1[(2 * w0k2) * 64 + nn], fc_w1[(2 * w0k2 + 1) * 64 + nn]);
        u32 hi = packh2(fc_w1[(2 * w1k2) * 64 + nn], fc_w1[(2 * w1k2 + 1) * 64 + nn]);
        u32 dst = ((u32)(nn >> 3) * 4 + (u32)kt) * 32 + (u32)(nn & 7) * 4 + (u32)cc;
        *(u64 *)(smraw + OFFB_W1P + dst * 8) = (u64)lo | ((u64)hi << 32);
    }
    // ---- stage W2: [nt2][kt][lane] u64
    for (int i = tid; i < 16 * 16; i += 128) {
        int nn = i >> 4, idx = i & 15;
        int kt = idx >> 2, cc = idx & 3;
        int w0k2 = 8 * kt + cc, w1k2 = w0k2 + 4;
        u32 lo = packh2(fc_w2[(2 * w0k2) * 16 + nn], fc_w2[(2 * w0k2 + 1) * 16 + nn]);
        u32 hi = packh2(fc_w2[(2 * w1k2) * 16 + nn], fc_w2[(2 * w1k2 + 1) * 16 + nn]);
        u32 dst = ((u32)(nn >> 3) * 4 + (u32)kt) * 32 + (u32)(nn & 7) * 4 + (u32)cc;
        *(u64 *)(smraw + OFFB_W2P + dst * 8) = (u64)lo | ((u64)hi << 32);
    }
    if (tid < 64) *(float *)(smraw + OFFB_B1 + tid * 4) = fc_b1[tid];
    if (tid < 16) *(float *)(smraw + OFFB_B2 + tid * 4) = fc_b2[tid];
    __syncthreads();

    const float *sB1 = (const float *)(smraw + OFFB_B1);
    const float *sB2 = (const float *)(smraw + OFFB_B2);
    u32 *sx = (u32 *)(smraw + OFFB_STAGE) + warp * 1024;
    float *sxf = (float *)sx;
    const u32 sx_addr = smem_u32(sx);
    u32 *meta = (u32 *)(smraw + OFFB_META) + warp * 384;  // [32][12]
    const u32 meta_addr = smem_u32(meta);

    // ldmatrix role precompute
    const int mi = lane >> 3, rr = lane & 7;
    const int rotA = ROT(rr);
    const u32 baseA = sx_addr + (u32)(((mi & 1) * 8 + rr) * 128);
    const u32 baseB = baseA + 16 * 128;
    const int khalf = (mi >> 1) * 4;

    // prefetch first tile's coords
    int tile = blockIdx.x;
    float2 pco, dco;
    {
        int pc0 = min(tile * 128 + warp * 32 + lane, n - 1);
        pco = *(const float2 *)(pos + 2 * pc0);
        dco = *(const float2 *)(dir + 2 * pc0);
    }

    for (; tile < ntiles; tile += gridDim.x) {
        const int p = tile * 128 + warp * 32 + lane;
        float2 pcur = pco, dcur = dco;
        int tnext = tile + gridDim.x;
        if (tnext < ntiles) {
            int pcn = min(tnext * 128 + warp * 32 + lane, n - 1);
            pco = *(const float2 *)(pos + 2 * pcn);
            dco = *(const float2 *)(dir + 2 * pcn);
        }

        // ===== owner: encode -> packed u32 corner metadata (cell16 | f16w<<16) =====
        {
            float gx[2], gy[2];
            encode(pcur.x, pcur.y, gx[0], gy[0]);
            encode(dcur.x, dcur.y, gx[1], gy[1]);
#pragma unroll
            for (int g = 0; g < 2; g++) {
                float x = gx[g], y = gy[g];
                int x0 = min((int)x, 255), y0 = min((int)y, 255);
                float xf = x - (float)x0, yf = y - (float)y0;
                int x1 = min(x0 + 1, 255), y1 = min(y0 + 1, 255);
                u32 c0 = (u32)(y0 * 256 + x0);
                u32 c1 = (u32)(y0 * 256 + x1);
                u32 c2 = (u32)(y1 * 256 + x0);
                u32 c3 = (u32)(y1 * 256 + x1);
                float w0 = (1.0f - xf) * (1.0f - yf);
                float w1 = xf * (1.0f - yf);
                float w2 = (1.0f - xf) * yf;
                float w3 = xf * yf;
                u32 m0 = c0 | (packh2(w0, 0.0f) << 16);
                u32 m1 = c1 | (packh2(w1, 0.0f) << 16);
                u32 m2 = c2 | (packh2(w2, 0.0f) << 16);
                u32 m3 = c3 | (packh2(w3, 0.0f) << 16);
                sts128u(meta_addr + (u32)(lane * 48 + g * 16), m0, m1, m2, m3);
            }
        }
        __syncwarp();

        // ===== loader: 4 lanes/row, LDG.128 gather + fp16x2 blend -> rotated stage =====
#pragma unroll 1
        for (int g = 0; g < 2; g++) {
            const char *gbase = (const char *)(g_f16 + (u32)g * 1048576u);
#pragma unroll
            for (int i = 0; i < 4; i++) {
                int row = i * 8 + r;
                uint4 mg = *(const uint4 *)(meta + row * 12 + g * 4);
                u32 a0 = 0, a1 = 0, a2 = 0, a3 = 0;
#pragma unroll
                for (int cc = 0; cc < 4; cc++) {
                    u32 m = (cc == 0) ? mg.x : (cc == 1) ? mg.y : (cc == 2) ? mg.z : mg.w;
                    u32 wb = prmt_hi2(m);
                    u32 off = (m & 0xFFFFu) << 6;
                    uint4 v = __ldg((const uint4 *)(gbase + off) + c);
                    a0 = hfma2(v.x, wb, a0);
                    a1 = hfma2(v.y, wb, a1);
                    a2 = hfma2(v.z, wb, a2);
                    a3 = hfma2(v.w, wb, a3);
                }
                int word = row * 32 + ((g * 16 + 4 * c + ROT(row)) & 31);
                sts128u(sx_addr + (u32)(word * 4), a0, a1, a2, a3);
            }
        }
        __syncwarp();

        // ===== FC1 + FC2 fused: A-frags hoisted once, nt-quarters (d1[16]) =====
        u32 A[32];  // [kt][8]
#pragma unroll
        for (int kt = 0; kt < 4; kt++) {
            u32 wo = (u32)(((8 * kt + khalf + rotA) & 31) * 4);
            ldsm4(A[kt * 8 + 0], A[kt * 8 + 1], A[kt * 8 + 2], A[kt * 8 + 3], baseA + wo);
            ldsm4(A[kt * 8 + 4], A[kt * 8 + 5], A[kt * 8 + 6], A[kt * 8 + 7], baseB + wo);
        }

        float d2[16];
#pragma unroll
        for (int q = 0; q < 16; q++) d2[q] = 0.0f;

#pragma unroll 1
        for (int q = 0; q < 4; q++) {   // nt pair (2q, 2q+1); FC2 k-tile = q
            float d1[16];
#pragma unroll
            for (int z = 0; z < 16; z++) d1[z] = 0.0f;
#pragma unroll
            for (int kt = 0; kt < 4; kt++) {
#pragma unroll
                for (int ntp = 0; ntp < 2; ntp++) {
                    int nt = 2 * q + ntp;
                    u64 bb = *(const u64 *)(smraw + OFFB_W1P +
                                            (u32)(((nt * 4 + kt) * 32 + lane) * 8));
                    u32 b0 = (u32)bb, b1 = (u32)(bb >> 32);
                    mma_f16(d1 + ntp * 8, A[kt * 8 + 0], A[kt * 8 + 1], A[kt * 8 + 2],
                            A[kt * 8 + 3], b0, b1);
                    mma_f16(d1 + ntp * 8 + 4, A[kt * 8 + 4], A[kt * 8 + 5], A[kt * 8 + 6],
                            A[kt * 8 + 7], b0, b1);
                }
            }
            // FC2 partial: this quarter's D1 = A-frags for k-tile q
            int ntA0 = 2 * q, ntA1 = 2 * q + 1;
            float blo0 = sB1[8 * ntA0 + 2 * c];
            float bhi0 = sB1[8 * ntA0 + 2 * c + 1];
            float blo1 = sB1[8 * ntA1 + 2 * c];
            float bhi1 = sB1[8 * ntA1 + 2 * c + 1];
            u32 a0 = packh2(leaky(d1[0] + blo0), leaky(d1[1] + bhi0));
            u32 a1 = packh2(leaky(d1[2] + blo0), leaky(d1[3] + bhi0));
            u32 a2 = packh2(leaky(d1[8] + blo1), leaky(d1[9] + bhi1));
            u32 a3 = packh2(leaky(d1[10] + blo1), leaky(d1[11] + bhi1));
            u32 a10 = packh2(leaky(d1[4] + blo0), leaky(d1[5] + bhi0));
            u32 a11 = packh2(leaky(d1[6] + blo0), leaky(d1[7] + bhi0));
            u32 a12 = packh2(leaky(d1[12] + blo1), leaky(d1[13] + bhi1));
            u32 a13 = packh2(leaky(d1[14] + blo1), leaky(d1[15] + bhi1));
#pragma unroll
            for (int nt2 = 0; nt2 < 2; nt2++) {
                u64 bb = *(const u64 *)(smraw + OFFB_W2P +
                                        (u32)(((nt2 * 4 + q) * 32 + lane) * 8));
                u32 b0 = (u32)bb, b1 = (u32)(bb >> 32);
                mma_f16(d2 + nt2 * 8, a0, a1, a2, a3, b0, b1);
                mma_f16(d2 + nt2 * 8 + 4, a10, a11, a12, a13, b0, b1);
            }
        }
        __syncwarp();

        // ===== H2 = leaky(D2 + b2) -> f32 restage (rotated) =====
        {
            int rotH = ROT(r);
#pragma unroll
            for (int nt = 0; nt < 2; nt++) {
                float blo = sB2[8 * nt + 2 * c];
                float bhi = sB2[8 * nt + 2 * c + 1];
                const float *dd = d2 + nt * 8;
                int wo = (8 * nt + 2 * c + rotH) & 31;
                *(u64 *)&sxf[(r) * 32 + wo] = pack2(leaky(dd[0] + blo), leaky(dd[1] + bhi));
                *(u64 *)&sxf[(r + 8) * 32 + wo] = pack2(leaky(dd[2] + blo), leaky(dd[3] + bhi));
                *(u64 *)&sxf[(r + 16) * 32 + wo] = pack2(leaky(dd[4] + blo), leaky(dd[5] + bhi));
                *(u64 *)&sxf[(r + 24) * 32 + wo] = pack2(leaky(dd[6] + blo), leaky(dd[7] + bhi));
            }
        }
        __syncwarp();

        // ===== head: FC3 (16->8, cmem uniform) + FC4 + sigmoid*255 =====
        float a2[16];
        {
            int rotL = ROT(lane);
#pragma unroll
            for (int q = 0; q < 4; q++) {
                float4 v = *(const float4 *)&sxf[lane * 32 + ((4 * q + rotL) & 31)];
                a2[4 * q + 0] = v.x;
                a2[4 * q + 1] = v.y;
                a2[4 * q + 2] = v.z;
                a2[4 * q + 3] = v.w;
            }
        }
        u64 h3[4];
#pragma unroll
        for (int q = 0; q < 4; q++) h3[q] = pack2(cB3[2 * q], cB3[2 * q + 1]);
#pragma unroll
        for (int j = 0; j < 16; j++) {
            float a = a2[j];
            u64 av = pack2(a, a);
            const ulonglong2 *w = (const ulonglong2 *)(cW3 + j * 8);
            ulonglong2 w01 = w[0], w23 = w[1];
            fma2(h3[0], av, w01.x);
            fma2(h3[1], av, w01.y);
            fma2(h3[2], av, w23.x);
            fma2(h3[3], av, w23.y);
        }
        float o0 = cB4[0], o1 = cB4[1], o2 = cB4[2];
#pragma unroll
        for (int q = 0; q < 4; q++) {
            float2 v = unpack2(h3[q]);
            float a0 = leaky(v.x), a1 = leaky(v.y);
            int i0 = 2 * q, i1 = 2 * q + 1;
            o0 = fmaf(a0, cW4[i0 * 3 + 0], o0);
            o1 = fmaf(a0, cW4[i0 * 3 + 1], o1);
            o2 = fmaf(a0, cW4[i0 * 3 + 2], o2);
            o0 = fmaf(a1, cW4[i1 * 3 + 0], o0);
            o1 = fmaf(a1, cW4[i1 * 3 + 1], o1);
            o2 = fmaf(a1, cW4[i1 * 3 + 2], o2);
        }
        o0 = sigmoidf(leaky(o0)) * 255.0f;
        o1 = sigmoidf(leaky(o1)) * 255.0f;
        o2 = sigmoidf(leaky(o2)) * 255.0f;

        if (p < n) {
            out[p * 3 + 0] = o0;
            out[p * 3 + 1] = o1;
            out[p * 3 + 2] = o2;
        }
        __syncwarp();  // stage/meta reuse across tiles
    }
}

extern "C" void kernel_launch(void *const *d_in, const int *in_sizes, int n_in,
                              void *d_out, int out_size)
{
    const float *pos = (const float *)d_in[0];
    const float *dir = (const float *)d_in[1];
    const float *pos_grid = (const float *)d_in[2];
    const float *dir_grid = (const float *)d_in[3];

    cudaMemcpyToSymbolAsync(cEnc, d_in[4], 8 * sizeof(float), 0, cudaMemcpyDeviceToDevice, 0);
    cudaMemcpyToSymbolAsync(cEnc, d_in[5], 4 * sizeof(float), 8 * sizeof(float), cudaMemcpyDeviceToDevice, 0);
    cudaMemcpyToSymbolAsync(cEnc, d_in[6], 12 * sizeof(float), 12 * sizeof(float), cudaMemcpyDeviceToDevice, 0);
    cudaMemcpyToSymbolAsync(cEnc, d_in[7], 3 * sizeof(float), 24 * sizeof(float), cudaMemcpyDeviceToDevice, 0);
    cudaMemcpyToSymbolAsync(cW3, d_in[12], 16 * 8 * sizeof(float), 0, cudaMemcpyDeviceToDevice, 0);
    cudaMemcpyToSymbolAsync(cB3, d_in[13], 8 * sizeof(float), 0, cudaMemcpyDeviceToDevice, 0);
    cudaMemcpyToSymbolAsync(cW4, d_in[14], 8 * 3 * sizeof(float), 0, cudaMemcpyDeviceToDevice, 0);
    cudaMemcpyToSymbolAsync(cB4, d_in[15], 3 * sizeof(float), 0, cudaMemcpyDeviceToDevice, 0);

    convert_grids<<<4096, 256>>>(pos_grid, dir_grid);

    cudaFuncSetAttribute(gridnet_cfb, cudaFuncAttributeMaxDynamicSharedMemorySize, DYN_BYTES);

    float *out = (float *)d_out;
    int n = in_sizes[0] / 2;
    int ntiles = (n + 127) / 128;
    int blocks = 148 * 5;
    if (blocks > ntiles) blocks = ntiles;
    gridnet_cfb<<<blocks, 128, DYN_BYTES>>>(
        pos, dir,
        (const float *)d_in[8], (const float *)d_in[9],
        (const float *)d_in[10], (const float *)d_in[11],
        out, n, ntiles);
}